// round 13
// baseline (speedup 1.0000x reference)
#include <cuda_runtime.h>
#include <cuda_fp16.h>
#include <cstdint>

#define L_LAYERS 6
#define DIMV     40
#define HV       128
#define ADIMV    20
#define BTOT     131072
#define MTILE    64
#define NTHR     256

// fp16 packed weight segments per layer (uint32 words), all B-frag order
#define OA  0         // W1 za rows 0..19 (pad 32) : 2 ks16 x 8 ntp x 32 x 4
#define OC  2048      // W1 ctx rows 20..147       : 8 ks16 x 8 ntp x 32 x 4
#define OT  10240     // W1 te  rows 148..275
#define O2  18432     // W2
#define O3  26624     // W3
#define O4  34816     // [Ws|Wt|0] : 8 ks16 x 6 nt x 32 x 2
#define WPH_L 37888

__device__ unsigned g_wph[6 * WPH_L];
__device__ unsigned g_apk[2 * (size_t)BTOT * 64];   // ctx|te fp16 A-frag order (uint4 blocks)

__device__ __forceinline__ unsigned h2pack(float a, float b) {
    __half2 h = __floats2half2_rn(a, b);
    return *reinterpret_cast<unsigned*>(&h);
}
__device__ __forceinline__ void mma16(float c[4], const unsigned a[4], unsigned b0, unsigned b1) {
    asm volatile(
        "mma.sync.aligned.m16n8k16.row.col.f32.f16.f16.f32 "
        "{%0,%1,%2,%3}, {%4,%5,%6,%7}, {%8,%9}, {%0,%1,%2,%3};\n"
        : "+f"(c[0]), "+f"(c[1]), "+f"(c[2]), "+f"(c[3])
        : "r"(a[0]), "r"(a[1]), "r"(a[2]), "r"(a[3]), "r"(b0), "r"(b1));
}
__device__ __forceinline__ float silu(float v) {
    return __fdividef(v, 1.0f + __expf(-v));
}

// ---------------------------------------------------------------------------
// prep: all weights fp16, fragment order
// ---------------------------------------------------------------------------
__global__ void prep_w_kernel(const float* __restrict__ W1, const float* __restrict__ W2,
                              const float* __restrict__ W3, const float* __restrict__ Ws,
                              const float* __restrict__ Wt) {
    int i = blockIdx.x * blockDim.x + threadIdx.x;
    if (i >= 6 * WPH_L) return;
    int layer = i / WPH_L;
    int w = i - layer * WPH_L;
    const float* w1b = W1 + (size_t)layer * 276 * HV;

    if (w < OC) {                     // za segment: B-frag, K rows 0..19 (pad to 32)
        int idx = w;
        int comp = idx & 3, lane = (idx >> 2) & 31;
        int ntp = (idx >> 7) & 7, ks = idx >> 10;      // ks 0..1
        int g = lane >> 2, t4 = lane & 3;
        int col = (ntp * 2 + (comp >> 1)) * 8 + g;
        int k0 = ks * 16 + (comp & 1) * 8 + 2 * t4;
        float v0 = 0.0f, v1 = 0.0f;
        if (k0 < ADIMV) { v0 = w1b[k0 * HV + col]; v1 = w1b[(k0 + 1) * HV + col]; }
        g_wph[i] = h2pack(v0, v1);
    } else if (w < O4) {              // ctx / te / W2 / W3
        int seg = (w - OC) / 8192;
        int idx = (w - OC) - seg * 8192;
        int comp = idx & 3, lane = (idx >> 2) & 31;
        int ntp = (idx >> 7) & 7, ks = idx >> 10;
        int g = lane >> 2, t4 = lane & 3;
        int col = (ntp * 2 + (comp >> 1)) * 8 + g;
        int k0 = ks * 16 + (comp & 1) * 8 + 2 * t4;
        float v0, v1;
        if (seg == 0)      { v0 = w1b[(ADIMV + k0) * HV + col];       v1 = w1b[(ADIMV + k0 + 1) * HV + col]; }
        else if (seg == 1) { v0 = w1b[(ADIMV + 128 + k0) * HV + col]; v1 = w1b[(ADIMV + 128 + k0 + 1) * HV + col]; }
        else if (seg == 2) { const float* p = W2 + (size_t)layer * HV * HV;
                             v0 = p[k0 * HV + col]; v1 = p[(k0 + 1) * HV + col]; }
        else               { const float* p = W3 + (size_t)layer * HV * HV;
                             v0 = p[k0 * HV + col]; v1 = p[(k0 + 1) * HV + col]; }
        g_wph[i] = h2pack(v0, v1);
    } else {                          // [Ws|Wt|0], N=48
        int idx = w - O4;
        int comp = idx & 1, lane = (idx >> 1) & 31;
        int rest = idx >> 6;
        int nt = rest % 6, ks = rest / 6;
        int g = lane >> 2, t4 = lane & 3;
        int col = nt * 8 + g;
        int k0 = ks * 16 + comp * 8 + 2 * t4;
        float v0 = 0.0f, v1 = 0.0f;
        if (col < ADIMV) {
            const float* p = Ws + (size_t)layer * HV * ADIMV;
            v0 = p[k0 * ADIMV + col]; v1 = p[(k0 + 1) * ADIMV + col];
        } else if (col < DIMV) {
            const float* p = Wt + (size_t)layer * HV * ADIMV;
            v0 = p[k0 * ADIMV + col - ADIMV]; v1 = p[(k0 + 1) * ADIMV + col - ADIMV];
        }
        g_wph[i] = h2pack(v0, v1);
    }
}

// ctx/te -> fp16 A-frag order (uint4 blocks: comp fastest)
__global__ void prep_a_kernel(const float* __restrict__ ctx, const float* __restrict__ te) {
    size_t i = (size_t)blockIdx.x * blockDim.x + threadIdx.x;
    const size_t seg_sz = (size_t)BTOT * 64;
    if (i >= 2 * seg_sz) return;
    int seg = (int)(i / seg_sz);
    size_t idx = i - (size_t)seg * seg_sz;
    int comp = (int)(idx & 3);
    int lane = (int)((idx >> 2) & 31);
    int kb = (int)((idx >> 7) & 7);
    size_t rb16 = idx >> 10;
    int g = lane >> 2, t4 = lane & 3;
    size_t row = rb16 * 16 + g + 8 * (comp & 1);
    int kcol = kb * 16 + 8 * (comp >> 1) + 2 * t4;
    const float* src = seg ? te : ctx;
    g_apk[i] = h2pack(src[row * HV + kcol], src[row * HV + kcol + 1]);
}

// ---------------------------------------------------------------------------
// GEMM pieces: warp tile 16x64 (4 wm x 2 wn over 64x128), A uint4 frags
// ---------------------------------------------------------------------------
template <int NKS>
__device__ __forceinline__ void gemm_smem(float acc[8][4], const uint4* __restrict__ abase,
                                          const uint4* __restrict__ bp, int wn, int lane) {
#pragma unroll
    for (int ks = 0; ks < NKS; ks++) {
        uint4 av = abase[ks * 32];
        unsigned a[4] = {av.x, av.y, av.z, av.w};
        const uint4* bb = bp + (ks * 8 + wn * 4) * 32 + lane;
#pragma unroll
        for (int ntp = 0; ntp < 4; ntp++) {
            uint4 bv = __ldg(bb + ntp * 32);
            mma16(acc[2 * ntp], a, bv.x, bv.y);
            mma16(acc[2 * ntp + 1], a, bv.z, bv.w);
        }
    }
}

__device__ __forceinline__ void gemm_pk(float acc[8][4], const uint4* __restrict__ abase,
                                        const uint4* __restrict__ bp, int wn, int lane) {
#pragma unroll
    for (int ks = 0; ks < 8; ks++) {
        uint4 av = __ldg(abase + ks * 32);
        unsigned a[4] = {av.x, av.y, av.z, av.w};
        const uint4* bb = bp + (ks * 8 + wn * 4) * 32 + lane;
#pragma unroll
        for (int ntp = 0; ntp < 4; ntp++) {
            uint4 bv = __ldg(bb + ntp * 32);
            mma16(acc[2 * ntp], a, bv.x, bv.y);
            mma16(acc[2 * ntp + 1], a, bv.z, bv.w);
        }
    }
}

// epilogue: silu+bias -> h uint4-frag store (STS.64)
__device__ __forceinline__ void epi_silu_h(float acc[8][4], const float* __restrict__ bias,
                                           unsigned* __restrict__ hwu,
                                           int wm, int wn, int lane, int t4) {
#pragma unroll
    for (int nt = 0; nt < 8; nt++) {
        int c0 = wn * 64 + nt * 8 + t4 * 2;
        float bb0 = __ldg(bias + c0);
        float bb1 = __ldg(bias + c0 + 1);
        float v0 = silu(acc[nt][0] + bb0);
        float v1 = silu(acc[nt][1] + bb1);
        float v2 = silu(acc[nt][2] + bb0);
        float v3 = silu(acc[nt][3] + bb1);
        int kb = wn * 4 + (nt >> 1);
        int cb = (nt & 1) * 2;
        uint2 pk;
        pk.x = h2pack(v0, v1);
        pk.y = h2pack(v2, v3);
        *reinterpret_cast<uint2*>(hwu + ((((wm * 8 + kb) * 32 + lane) << 2) + cb)) = pk;
    }
}

__device__ __forceinline__ void zacc8(float acc[8][4]) {
#pragma unroll
    for (int nt = 0; nt < 8; nt++)
#pragma unroll
        for (int e = 0; e < 4; e++) acc[nt][e] = 0.0f;
}

// ---------------------------------------------------------------------------
__global__ void __launch_bounds__(NTHR)
flow_fused_kernel(const float* __restrict__ xin, float* __restrict__ zfinal,
                  float* __restrict__ ldfinal,
                  const float* __restrict__ b1, const float* __restrict__ b2,
                  const float* __restrict__ b3, const float* __restrict__ bsw,
                  const float* __restrict__ btw,
                  const int* __restrict__ perm, const int* __restrict__ idxa,
                  const int* __restrict__ idxb) {
    __shared__ unsigned hwu[4096];       // h frags: ((wm*8+kb)*32+lane) uint4
    __shared__ unsigned zawu[1024];      // za frags: ((r16*2+kb)*32+lane) uint4
    __shared__ float st_s[64 * 41];
    __shared__ float z_s[64 * DIMV];
    __shared__ int sga_all[120], sgb_all[120], sia_all[120], sib_all[120];

    const int tid = threadIdx.x;
    const int warp = tid >> 5, lane = tid & 31;
    const int t4 = lane & 3;
    const int wm = warp >> 1, wn = warp & 1;
    const int rb = blockIdx.x * MTILE;
    const int rb16 = (rb >> 4) + wm;

    if (tid < 120) {
        int l = tid / 20, k = tid - l * 20;
        int v = idxa[l * ADIMV + k];
        sia_all[tid] = v;
        sga_all[tid] = perm[l * DIMV + v];
    } else if (tid < 240) {
        int u = tid - 120;
        int l = u / 20, k = u - l * 20;
        int v = idxb[l * ADIMV + k];
        sib_all[u] = v;
        sgb_all[u] = perm[l * DIMV + v];
    }
    for (int i = tid; i < MTILE * DIMV; i += NTHR)
        z_s[i] = xin[(size_t)rb * DIMV + i];

    const uint4* hw4  = reinterpret_cast<const uint4*>(hwu);
    const uint4* zaw4 = reinterpret_cast<const uint4*>(zawu);

    float ldacc = 0.0f;

    for (int layer = 0; layer < L_LAYERS; layer++) {
        const unsigned* wl = g_wph + layer * WPH_L;
        const int* sga = sga_all + layer * 20;
        const int* sgb = sgb_all + layer * 20;
        const int* sia = sia_all + layer * 20;
        const int* sib = sib_all + layer * 20;

        __syncthreads();   // z_s (and idx on layer 0) ready

        // build za fp16 A-frags from z_s (1024 words total: 4 r16 x 2 kb x 32 ln x 4 comp)
        for (int i = tid; i < 1024; i += NTHR) {
            int comp = i & 3, ln = (i >> 2) & 31;
            int kb = (i >> 7) & 1, r16 = i >> 8;
            int gg = ln >> 2, tt = ln & 3;
            int r = r16 * 16 + gg + 8 * (comp & 1);
            int k0 = kb * 16 + (comp >> 1) * 8 + 2 * tt;
            unsigned val = 0u;
            if (k0 < ADIMV)
                val = h2pack(z_s[r * DIMV + sga[k0]], z_s[r * DIMV + sga[k0 + 1]]);
            zawu[i] = val;
        }
        __syncthreads();

        float acc[8][4];
        zacc8(acc);

        // GEMM1: za (smem frags) + ctx + te (gmem prepacked)
        gemm_smem<2>(acc, zaw4 + (wm * 2) * 32 + lane,
                     reinterpret_cast<const uint4*>(wl + OA), wn, lane);
        gemm_pk(acc, reinterpret_cast<const uint4*>(g_apk) + (size_t)rb16 * 8 * 32 + lane,
                reinterpret_cast<const uint4*>(wl + OC), wn, lane);
        gemm_pk(acc, reinterpret_cast<const uint4*>(g_apk + (size_t)BTOT * 64) + (size_t)rb16 * 8 * 32 + lane,
                reinterpret_cast<const uint4*>(wl + OT), wn, lane);
        epi_silu_h(acc, b1 + layer * HV, hwu, wm, wn, lane, t4);
        __syncthreads();

        // GEMM2
        zacc8(acc);
        gemm_smem<8>(acc, hw4 + (wm * 8) * 32 + lane,
                     reinterpret_cast<const uint4*>(wl + O2), wn, lane);
        __syncthreads();
        epi_silu_h(acc, b2 + layer * HV, hwu, wm, wn, lane, t4);
        __syncthreads();

        // GEMM3
        zacc8(acc);
        gemm_smem<8>(acc, hw4 + (wm * 8) * 32 + lane,
                     reinterpret_cast<const uint4*>(wl + O3), wn, lane);
        __syncthreads();
        epi_silu_h(acc, b3 + layer * HV, hwu, wm, wn, lane, t4);
        __syncthreads();

        // GEMM4: N=48, warp tile 16x24
        float a4[3][4];
#pragma unroll
        for (int nt = 0; nt < 3; nt++)
#pragma unroll
            for (int e = 0; e < 4; e++) a4[nt][e] = 0.0f;
        {
            const uint2* bp4 = reinterpret_cast<const uint2*>(wl + O4);
#pragma unroll
            for (int ks = 0; ks < 8; ks++) {
                uint4 av = hw4[(wm * 8 + ks) * 32 + lane];
                unsigned a[4] = {av.x, av.y, av.z, av.w};
#pragma unroll
                for (int nt = 0; nt < 3; nt++) {
                    uint2 bv = __ldg(bp4 + (ks * 6 + wn * 3 + nt) * 32 + lane);
                    mma16(a4[nt], a, bv.x, bv.y);
                }
            }
        }
        // epilogue4 -> st_s (fp32)
        {
            const float* bsl = bsw + layer * ADIMV;
            const float* btl = btw + layer * ADIMV;
            int gg = lane >> 2;
#pragma unroll
            for (int nt = 0; nt < 3; nt++)
#pragma unroll
                for (int e = 0; e < 4; e++) {
                    int row = wm * 16 + gg + ((e >= 2) ? 8 : 0);
                    int col = wn * 24 + nt * 8 + t4 * 2 + (e & 1);
                    if (col < DIMV) {
                        float v = a4[nt][e];
                        if (col < ADIMV) {
                            v += __ldg(bsl + col);
                            v = fminf(fmaxf(v, -2.0f), 2.0f);
                        } else {
                            v += __ldg(btl + col - ADIMV);
                        }
                        st_s[row * 41 + col] = v;
                    }
                }
        }
        __syncthreads();

        // coupling: 4 threads/row, read-then-write with warp sync
        {
            int r = tid >> 2, q = tid & 3;
            float zav[5], zbv[5];
#pragma unroll
            for (int j = 0; j < 5; j++) {
                int k = q * 5 + j;
                zav[j] = z_s[r * DIMV + sga[k]];
                zbv[j] = z_s[r * DIMV + sgb[k]];
            }
            __syncwarp();
            const float* strow = st_s + r * 41;
            float ssum = 0.0f;
#pragma unroll
            for (int j = 0; j < 5; j++) {
                int k = q * 5 + j;
                float s = strow[k];
                float t = strow[ADIMV + k];
                ssum += s;
                z_s[r * DIMV + sib[k]] = zbv[j] * __expf(s) + t;
                z_s[r * DIMV + sia[k]] = zav[j];
            }
            ssum += __shfl_xor_sync(0xffffffffu, ssum, 1);
            ssum += __shfl_xor_sync(0xffffffffu, ssum, 2);
            ldacc += ssum;
        }
    }

    __syncthreads();
    for (int i = tid; i < MTILE * DIMV; i += NTHR)
        zfinal[(size_t)rb * DIMV + i] = z_s[i];
    if ((tid & 3) == 0)
        ldfinal[(size_t)rb + (tid >> 2)] = ldacc;
}

extern "C" void kernel_launch(void* const* d_in, const int* in_sizes, int n_in,
                              void* d_out, int out_size) {
    const float* x   = (const float*)d_in[0];
    const float* ctx = (const float*)d_in[1];
    const float* te  = (const float*)d_in[2];
    const float* W1  = (const float*)d_in[3];
    const float* b1  = (const float*)d_in[4];
    const float* W2  = (const float*)d_in[5];
    const float* b2  = (const float*)d_in[6];
    const float* W3  = (const float*)d_in[7];
    const float* b3  = (const float*)d_in[8];
    const float* Ws  = (const float*)d_in[9];
    const float* bs  = (const float*)d_in[10];
    const float* Wt  = (const float*)d_in[11];
    const float* bt  = (const float*)d_in[12];
    const int* perm  = (const int*)d_in[13];
    const int* ia    = (const int*)d_in[14];
    const int* ib    = (const int*)d_in[15];

    float* outz  = (float*)d_out;
    float* outld = outz + (size_t)BTOT * DIMV;

    prep_w_kernel<<<(6 * WPH_L + 255) / 256, 256>>>(W1, W2, W3, Ws, Wt);
    {
        size_t tot = 2 * (size_t)BTOT * 64;
        prep_a_kernel<<<(unsigned)((tot + 255) / 256), 256>>>(ctx, te);
    }

    dim3 grid(BTOT / MTILE), blk(NTHR);
    flow_fused_kernel<<<grid, blk>>>(
        x, outz, outld, b1, b2, b3, bs, bt, perm, ia, ib);
    (void)in_sizes; (void)n_in; (void)out_size;
}